// round 6
// baseline (speedup 1.0000x reference)
#include <cuda_runtime.h>
#include <math.h>
#include <stdint.h>

#define D_      768
#define DFF_    3072
#define S_      512
#define B_      16
#define H_      12
#define DH_     64
#define L_      6
#define MTOK    (B_ * S_)   // 8192
#define EPS_    1e-5f
#define NQKV    (3 * D_)    // 2304

// ---------------- scratch (device globals; no allocation allowed) -------------
__device__ float g_h [MTOK * D_];
__device__ float g_q [MTOK * D_];
__device__ float g_k [MTOK * D_];
__device__ float g_v [MTOK * D_];
__device__ float g_o [MTOK * D_];
__device__ float g_t [MTOK * D_];
__device__ float g_ff[MTOK * DFF_];
// transposed weights Wt[N,K] fp32 (pre-rounded to tf32)
__device__ float g_qkvT[L_ * NQKV * D_];
__device__ float g_qkvB[L_ * NQKV];
__device__ float g_w1T[L_ * D_ * DFF_];
__device__ float g_w2T[L_ * DFF_ * D_];

// ======================= helpers ==============================================
__device__ __forceinline__ uint32_t smem_u32(const void* p) {
    uint32_t a;
    asm("{ .reg .u64 t; cvta.to.shared.u64 t, %1; cvt.u32.u64 %0, t; }" : "=r"(a) : "l"(p));
    return a;
}
__device__ __forceinline__ void cp16(uint32_t saddr, const void* g) {
    asm volatile("cp.async.cg.shared.global [%0], [%1], 16;" :: "r"(saddr), "l"(g));
}
#define CP_COMMIT()  asm volatile("cp.async.commit_group;" ::: "memory")
#define CP_WAIT1()   asm volatile("cp.async.wait_group 1;" ::: "memory")
#define CP_WAIT0()   asm volatile("cp.async.wait_group 0;" ::: "memory")

__device__ __forceinline__ uint32_t f2tf32(float x) {
    uint32_t u;
    asm("cvt.rna.tf32.f32 %0, %1;" : "=r"(u) : "f"(x));
    return u;
}
__device__ __forceinline__ void ldm_x4(uint32_t& r0, uint32_t& r1, uint32_t& r2,
                                       uint32_t& r3, uint32_t addr) {
    asm volatile("ldmatrix.sync.aligned.m8n8.x4.shared.b16 {%0,%1,%2,%3}, [%4];"
                 : "=r"(r0), "=r"(r1), "=r"(r2), "=r"(r3) : "r"(addr));
}
__device__ __forceinline__ void mma_tf32(
    float& c0, float& c1, float& c2, float& c3,
    uint32_t a0, uint32_t a1, uint32_t a2, uint32_t a3,
    uint32_t b0, uint32_t b1)
{
    asm volatile(
        "mma.sync.aligned.m16n8k8.row.col.f32.tf32.tf32.f32 "
        "{%0,%1,%2,%3}, {%4,%5,%6,%7}, {%8,%9}, {%0,%1,%2,%3};"
        : "+f"(c0), "+f"(c1), "+f"(c2), "+f"(c3)
        : "r"(a0), "r"(a1), "r"(a2), "r"(a3), "r"(b0), "r"(b1));
}

// ---------------- GEMM config --------------------------------------------------
#define BM      256
#define BN      128
#define BK      32
#define NSTG    3
#define PAD     36                          // floats per smem row (bank-conflict-free)
#define STG_A   (BM * PAD)                  // 9216 floats
#define STG_B   (BN * PAD)                  // 4608 floats
#define SMEM_GEMM ((NSTG * (STG_A + STG_B)) * 4)   // 165888 bytes

// ==== tf32 mma.sync GEMM: C[M, Ntot] = A[M,K] @ Wt[Ntot,K]^T + bias ===========
// Output routed per 128-col tile: tile mat = bn/Nper -> C0/C1/C2, col = bn%Nper,
// row stride Nper. For unfused GEMMs pass C0=C1=C2 and Nper=Ntot.
__global__ __launch_bounds__(256) void gemm_mma(
    const float* __restrict__ A, const float* __restrict__ Wt,
    const float* __restrict__ bias,
    float* __restrict__ C0, float* __restrict__ C1, float* __restrict__ C2,
    int Nper, int K, int relu)
{
    extern __shared__ float smem[];
    float* As = smem;
    float* Bs = smem + NSTG * STG_A;
    uint32_t sA = smem_u32(As);
    uint32_t sB = smem_u32(Bs);

    int tid  = threadIdx.x;
    int lane = tid & 31;
    int wid  = tid >> 5;
    int grp  = lane >> 2, tg = lane & 3;
    int bm = blockIdx.y * BM;
    int bn = blockIdx.x * BN;
    int m0 = (wid >> 1) * 64;    // warp M offset (0,64,128,192)
    int n0 = (wid & 1) * 64;     // warp N offset (0,64)

    int mat = bn / Nper;
    float* C = (mat == 0) ? C0 : (mat == 1) ? C1 : C2;
    int cn = bn - mat * Nper;

    uint32_t a_lane = ((((lane >> 3) & 1) * 8 + (lane & 7)) * PAD
                       + ((lane >> 4) & 1) * 4) * 4;
    uint32_t b_lane = ((((lane >> 4) & 1) * 8 + (lane & 7)) * PAD
                       + ((lane >> 3) & 1) * 4) * 4;
    uint32_t aw = sA + (uint32_t)(m0 * PAD) * 4 + a_lane;
    uint32_t bw = sB + (uint32_t)(n0 * PAD) * 4 + b_lane;

    float acc[4][8][4];
    #pragma unroll
    for (int i = 0; i < 4; i++)
        #pragma unroll
        for (int j = 0; j < 8; j++)
            #pragma unroll
            for (int q = 0; q < 4; q++) acc[i][j][q] = 0.f;

    const int nk = K / BK;

    #define LOAD_STAGE(s, k0) do {                                              \
        _Pragma("unroll")                                                       \
        for (int i = 0; i < 8; i++) {                                           \
            int ch = tid + i * 256;          /* A: 2048 chunks */               \
            int row = ch >> 3, kc = (ch & 7) * 4;                               \
            uint32_t off = (uint32_t)(((s) * STG_A + row * PAD + kc) * 4);      \
            cp16(sA + off, A + (size_t)(bm + row) * K + (k0) + kc);             \
        }                                                                       \
        _Pragma("unroll")                                                       \
        for (int i = 0; i < 4; i++) {                                           \
            int ch = tid + i * 256;          /* B: 1024 chunks */               \
            int row = ch >> 3, kc = (ch & 7) * 4;                               \
            uint32_t off = (uint32_t)(((s) * STG_B + row * PAD + kc) * 4);      \
            cp16(sB + off, Wt + (size_t)(bn + row) * K + (k0) + kc);            \
        }                                                                       \
        CP_COMMIT();                                                            \
    } while (0)

    LOAD_STAGE(0, 0);
    LOAD_STAGE(1, BK);

    for (int step = 0; step < nk; step++) {
        int cur = step % NSTG;
        if (step + 2 <= nk) { CP_WAIT1(); } else { CP_WAIT0(); }
        __syncthreads();

        int nxt = step + 2;
        if (nxt < nk) LOAD_STAGE(nxt % NSTG, nxt * BK);

        uint32_t abase = aw + (uint32_t)(cur * STG_A) * 4;
        uint32_t bbase = bw + (uint32_t)(cur * STG_B) * 4;

        #pragma unroll
        for (int kk = 0; kk < 4; kk++) {          // four k8 sub-steps
            uint32_t kboff = (uint32_t)kk * 32;   // 8 floats = 32 bytes
            uint32_t af[4][4];
            #pragma unroll
            for (int im = 0; im < 4; im++)
                ldm_x4(af[im][0], af[im][1], af[im][2], af[im][3],
                       abase + (uint32_t)(im * 16 * PAD) * 4 + kboff);
            uint32_t bf[4][4];
            #pragma unroll
            for (int t16 = 0; t16 < 4; t16++)
                ldm_x4(bf[t16][0], bf[t16][1], bf[t16][2], bf[t16][3],
                       bbase + (uint32_t)(t16 * 16 * PAD) * 4 + kboff);
            #pragma unroll
            for (int im = 0; im < 4; im++)
                #pragma unroll
                for (int t16 = 0; t16 < 4; t16++) {
                    mma_tf32(acc[im][2*t16][0], acc[im][2*t16][1],
                             acc[im][2*t16][2], acc[im][2*t16][3],
                             af[im][0], af[im][1], af[im][2], af[im][3],
                             bf[t16][0], bf[t16][1]);
                    mma_tf32(acc[im][2*t16+1][0], acc[im][2*t16+1][1],
                             acc[im][2*t16+1][2], acc[im][2*t16+1][3],
                             af[im][0], af[im][1], af[im][2], af[im][3],
                             bf[t16][2], bf[t16][3]);
                }
        }
        __syncthreads();
    }

    #pragma unroll
    for (int im = 0; im < 4; im++) {
        int row = bm + m0 + im * 16 + grp;
        #pragma unroll
        for (int in8 = 0; in8 < 8; in8++) {
            int colb = n0 + in8 * 8 + tg * 2;
            float2 bv = *(const float2*)&bias[bn + colb];
            int col = cn + colb;
            float2 v0, v1;
            v0.x = acc[im][in8][0] + bv.x;
            v0.y = acc[im][in8][1] + bv.y;
            v1.x = acc[im][in8][2] + bv.x;
            v1.y = acc[im][in8][3] + bv.y;
            if (relu) {
                v0.x = fmaxf(v0.x, 0.f); v0.y = fmaxf(v0.y, 0.f);
                v1.x = fmaxf(v1.x, 0.f); v1.y = fmaxf(v1.y, 0.f);
            }
            *(float2*)&C[(size_t)row * Nper + col]       = v0;
            *(float2*)&C[(size_t)(row + 8) * Nper + col] = v1;
        }
    }
    #undef LOAD_STAGE
}

// ---------------- weight transpose (+ tf32 rounding) ---------------------------
__global__ __launch_bounds__(256) void transpose_kernel(
    const float* __restrict__ src, float* __restrict__ dst, int R, int C)
{
    __shared__ float t[32][33];
    src += (size_t)blockIdx.z * R * C;
    dst += (size_t)blockIdx.z * R * C;
    int c0 = blockIdx.x * 32, r0 = blockIdx.y * 32;
    int x = threadIdx.x & 31, y = threadIdx.x >> 5;   // 32 x 8
    #pragma unroll
    for (int i = 0; i < 32; i += 8)
        t[y + i][x] = src[(size_t)(r0 + y + i) * C + c0 + x];
    __syncthreads();
    #pragma unroll
    for (int i = 0; i < 32; i += 8)
        dst[(size_t)(c0 + y + i) * R + r0 + x] = __uint_as_float(f2tf32(t[x][y + i]));
}

// merged QKV transpose into combined [L][2304][768]; z = mat*L + layer
__global__ __launch_bounds__(256) void transpose_qkv_kernel(
    const float* __restrict__ qw, const float* __restrict__ kw,
    const float* __restrict__ vw)
{
    __shared__ float t[32][33];
    int mat = blockIdx.z / L_, l = blockIdx.z % L_;
    const float* src = (mat == 0 ? qw : mat == 1 ? kw : vw) + (size_t)l * D_ * D_;
    float* dst = g_qkvT + (size_t)l * NQKV * D_ + (size_t)mat * D_ * D_;
    int c0 = blockIdx.x * 32, r0 = blockIdx.y * 32;
    int x = threadIdx.x & 31, y = threadIdx.x >> 5;
    #pragma unroll
    for (int i = 0; i < 32; i += 8)
        t[y + i][x] = src[(size_t)(r0 + y + i) * D_ + c0 + x];
    __syncthreads();
    #pragma unroll
    for (int i = 0; i < 32; i += 8)
        dst[(size_t)(c0 + y + i) * D_ + r0 + x] = __uint_as_float(f2tf32(t[x][y + i]));
}

// combined qkv bias
__global__ __launch_bounds__(256) void qkv_bias_kernel(
    const float* __restrict__ qb, const float* __restrict__ kb,
    const float* __restrict__ vb)
{
    int idx = blockIdx.x * 256 + threadIdx.x;
    if (idx >= L_ * NQKV) return;
    int l = idx / NQKV, j = idx % NQKV;
    int mat = j / D_, jj = j % D_;
    const float* src = (mat == 0 ? qb : mat == 1 ? kb : vb);
    g_qkvB[idx] = src[l * D_ + jj];
}

// ---------------- block reductions ---------------------------------------------
__device__ __forceinline__ float block_sum(float v, float* sred) {
    #pragma unroll
    for (int o = 16; o > 0; o >>= 1) v += __shfl_xor_sync(0xffffffffu, v, o);
    int wid = threadIdx.x >> 5, lid = threadIdx.x & 31;
    int nw = (blockDim.x + 31) >> 5;
    __syncthreads();
    if (lid == 0) sred[wid] = v;
    __syncthreads();
    if (wid == 0) {
        float t = (lid < nw) ? sred[lid] : 0.f;
        #pragma unroll
        for (int o = 16; o > 0; o >>= 1) t += __shfl_xor_sync(0xffffffffu, t, o);
        if (lid == 0) sred[0] = t;
    }
    __syncthreads();
    return sred[0];
}

// ---------------- input projection ---------------------------------------------
__global__ __launch_bounds__(256) void input_proj_kernel(
    const float* __restrict__ x, const float* __restrict__ in_w,
    const float* __restrict__ in_b, const float* __restrict__ pos)
{
    int t = blockIdx.x;
    int s = t & (S_ - 1);
    __shared__ float sx[32];
    if (threadIdx.x < 32) sx[threadIdx.x] = x[t * 32 + threadIdx.x];
    __syncthreads();
    for (int d = threadIdx.x; d < D_; d += 256) {
        float acc = in_b[d] + pos[s * D_ + d];
        #pragma unroll
        for (int kk = 0; kk < 32; kk++) acc = fmaf(sx[kk], in_w[kk * D_ + d], acc);
        g_h[t * D_ + d] = acc;
    }
}

// ---------------- flash attention: block per (q-tile 128, head, batch) ----------
#define QT   128
#define KTA  16

__global__ __launch_bounds__(128) void attn_flash(const int* __restrict__ lens)
{
    int qt = blockIdx.x, h = blockIdx.y, b = blockIdx.z;
    int len = lens[b];
    int qbase = qt * QT;
    if (qbase >= len) return;   // dead tile
    int tid = threadIdx.x;

    __shared__ float Qs[QT][68];
    __shared__ float Ks[KTA][64];
    __shared__ float Vs[KTA][64];

    #pragma unroll
    for (int i = 0; i < 16; i++) {
        int c = tid + i * 128;
        int r = c >> 4, col = (c & 15) * 4;
        *(float4*)&Qs[r][col] =
            *(const float4*)(g_q + (size_t)(b * S_ + qbase + r) * D_ + h * 64 + col);
    }
    __syncthreads();

    float4 qv[16];
    #pragma unroll
    for (int j = 0; j < 16; j++) qv[j] = *(const float4*)&Qs[tid][j * 4];

    bool valid = (qbase + tid) < len;
    float m = -1e30f, l = 0.f;
    float4 O[16];
    #pragma unroll
    for (int j = 0; j < 16; j++) O[j] = make_float4(0.f, 0.f, 0.f, 0.f);

    int nkt = (len + KTA - 1) / KTA;
    for (int kt = 0; kt < nkt; kt++) {
        int kbase = kt * KTA;
        __syncthreads();
        {
            int r = tid >> 3, col = (tid & 7) * 4;
            size_t g = (size_t)(b * S_ + kbase + r) * D_ + h * 64 + col;
            *(float4*)&Ks[r][col]      = *(const float4*)(g_k + g);
            *(float4*)&Ks[r][col + 32] = *(const float4*)(g_k + g + 32);
            *(float4*)&Vs[r][col]      = *(const float4*)(g_v + g);
            *(float4*)&Vs[r][col + 32] = *(const float4*)(g_v + g + 32);
        }
        __syncthreads();
        if (!valid) continue;

        int krem = len - kbase;
        float s[KTA];
        #pragma unroll
        for (int k = 0; k < KTA; k++) {
            float acc = 0.f;
            const float4* kr = (const float4*)&Ks[k][0];
            #pragma unroll
            for (int j = 0; j < 16; j++) {
                float4 kv = kr[j];
                acc = fmaf(kv.x, qv[j].x, acc);
                acc = fmaf(kv.y, qv[j].y, acc);
                acc = fmaf(kv.z, qv[j].z, acc);
                acc = fmaf(kv.w, qv[j].w, acc);
            }
            s[k] = (k < krem) ? acc * 0.125f : -1e30f;
        }
        float tmax = m;
        #pragma unroll
        for (int k = 0; k < KTA; k++) tmax = fmaxf(tmax, s[k]);
        float scale = __expf(m - tmax);
        float psum = 0.f;
        #pragma unroll
        for (int k = 0; k < KTA; k++) { s[k] = __expf(s[k] - tmax); psum += s[k]; }
        l = l * scale + psum;
        m = tmax;
        #pragma unroll
        for (int j = 0; j < 16; j++) {
            float4 o = O[j];
            o.x *= scale; o.y *= scale; o.z *= scale; o.w *= scale;
            #pragma unroll
            for (int k = 0; k < KTA; k++) {
                float4 vv = *(const float4*)&Vs[k][j * 4];
                o.x = fmaf(s[k], vv.x, o.x);
                o.y = fmaf(s[k], vv.y, o.y);
                o.z = fmaf(s[k], vv.z, o.z);
                o.w = fmaf(s[k], vv.w, o.w);
            }
            O[j] = o;
        }
    }

    if (valid) {
        float inv = 1.f / l;
        float* orow = g_o + (size_t)(b * S_ + qbase + tid) * D_ + h * 64;
        #pragma unroll
        for (int j = 0; j < 16; j++) {
            float4 o = O[j];
            o.x *= inv; o.y *= inv; o.z *= inv; o.w *= inv;
            *(float4*)(orow + j * 4) = o;
        }
    }
}

// ---------------- fused residual + layernorm ------------------------------------
__global__ __launch_bounds__(256) void ln_residual_kernel(
    const float* __restrict__ res, const float* __restrict__ gma,
    const float* __restrict__ bta)
{
    int t = blockIdx.x;
    int tid = threadIdx.x;
    __shared__ float sred[32];

    float vals[3];
    float s = 0.f;
    #pragma unroll
    for (int i = 0; i < 3; i++) {
        int d = tid + i * 256;
        float v = g_h[(size_t)t * D_ + d] + res[(size_t)t * D_ + d];
        vals[i] = v;
        s += v;
    }
    float mean = block_sum(s, sred) * (1.f / D_);

    float sq = 0.f;
    #pragma unroll
    for (int i = 0; i < 3; i++) { float c = vals[i] - mean; sq += c * c; }
    float var = block_sum(sq, sred) * (1.f / D_);
    float invstd = rsqrtf(var + EPS_);

    #pragma unroll
    for (int i = 0; i < 3; i++) {
        int d = tid + i * 256;
        g_h[(size_t)t * D_ + d] = (vals[i] - mean) * invstd * gma[d] + bta[d];
    }
}

// ---------------- pooling + output projection -----------------------------------
__global__ __launch_bounds__(256) void pool_kernel(
    const int* __restrict__ lens, const float* __restrict__ out_w,
    const float* __restrict__ out_b, float* __restrict__ out)
{
    int b = blockIdx.x;
    int tid = threadIdx.x;
    int len = lens[b];
    __shared__ float sred[32];

    float acc = 0.f;
    float invlen = 1.f / (float)len;
    #pragma unroll
    for (int i = 0; i < 3; i++) {
        int d = tid + i * 256;
        float s = 0.f;
        for (int si = 0; si < len; si++)
            s += g_h[(size_t)(b * S_ + si) * D_ + d];
        acc += (s * invlen) * out_w[d];
    }
    float tot = block_sum(acc, sred);
    if (tid == 0) out[b] = tot + out_b[0];
}

// ---------------- launch ---------------------------------------------------------
extern "C" void kernel_launch(void* const* d_in, const int* in_sizes, int n_in,
                              void* d_out, int out_size)
{
    const float* x     = (const float*)d_in[0];
    const int*   lens  = (const int*)  d_in[1];
    const float* in_w  = (const float*)d_in[2];
    const float* in_b  = (const float*)d_in[3];
    const float* pos   = (const float*)d_in[4];
    const float* qw    = (const float*)d_in[5];
    const float* qb    = (const float*)d_in[6];
    const float* kw    = (const float*)d_in[7];
    const float* kb    = (const float*)d_in[8];
    const float* vw    = (const float*)d_in[9];
    const float* vb    = (const float*)d_in[10];
    const float* w1    = (const float*)d_in[11];
    const float* b1    = (const float*)d_in[12];
    const float* w2    = (const float*)d_in[13];
    const float* b2    = (const float*)d_in[14];
    const float* ln1g  = (const float*)d_in[15];
    const float* ln1b  = (const float*)d_in[16];
    const float* ln2g  = (const float*)d_in[17];
    const float* ln2b  = (const float*)d_in[18];
    const float* out_w = (const float*)d_in[19];
    const float* out_b = (const float*)d_in[20];
    float* out = (float*)d_out;

    float *ph, *pq, *pk, *pv, *po, *pt, *pff;
    float *pqkvT, *pqkvB, *pw1T, *pw2T;
    cudaGetSymbolAddress((void**)&ph,  g_h);
    cudaGetSymbolAddress((void**)&pq,  g_q);
    cudaGetSymbolAddress((void**)&pk,  g_k);
    cudaGetSymbolAddress((void**)&pv,  g_v);
    cudaGetSymbolAddress((void**)&po,  g_o);
    cudaGetSymbolAddress((void**)&pt,  g_t);
    cudaGetSymbolAddress((void**)&pff, g_ff);
    cudaGetSymbolAddress((void**)&pqkvT, g_qkvT);
    cudaGetSymbolAddress((void**)&pqkvB, g_qkvB);
    cudaGetSymbolAddress((void**)&pw1T, g_w1T);
    cudaGetSymbolAddress((void**)&pw2T, g_w2T);

    cudaFuncSetAttribute(gemm_mma, cudaFuncAttributeMaxDynamicSharedMemorySize, SMEM_GEMM);

    transpose_qkv_kernel<<<dim3(24, 24, 3 * L_), 256>>>(qw, kw, vw);
    qkv_bias_kernel<<<(L_ * NQKV + 255) / 256, 256>>>(qb, kb, vb);
    transpose_kernel<<<dim3(96, 24, L_), 256>>>(w1, pw1T, D_, DFF_);
    transpose_kernel<<<dim3(24, 96, L_), 256>>>(w2, pw2T, DFF_, D_);

    input_proj_kernel<<<MTOK, 256>>>(x, in_w, in_b, pos);

    dim3 gQKV(NQKV / BN, MTOK / BM);   // (18, 32)
    dim3 gFF1(DFF_ / BN, MTOK / BM);   // (24, 32)
    dim3 gFF2(D_   / BN, MTOK / BM);   // (6, 32)
    dim3 gAttn(S_ / QT, H_, B_);       // (4, 12, 16)

    for (int l = 0; l < L_; l++) {
        const float* qkvTl = pqkvT + (size_t)l * NQKV * D_;
        const float* qkvBl = pqkvB + (size_t)l * NQKV;
        const float* w1Tl  = pw1T  + (size_t)l * D_ * DFF_;
        const float* w2Tl  = pw2T  + (size_t)l * DFF_ * D_;

        gemm_mma<<<gQKV, 256, SMEM_GEMM>>>(ph, qkvTl, qkvBl, pq, pk, pv, D_, D_, 0);

        attn_flash<<<gAttn, 128>>>(lens);

        ln_residual_kernel<<<MTOK, 256>>>(po, ln1g + l * D_, ln1b + l * D_);

        gemm_mma<<<gFF1, 256, SMEM_GEMM>>>(ph, w1Tl, b1 + l * DFF_, pff, pff, pff, DFF_, D_, 1);
        gemm_mma<<<gFF2, 256, SMEM_GEMM>>>(pff, w2Tl, b2 + l * D_, pt, pt, pt, D_, DFF_, 0);

        ln_residual_kernel<<<MTOK, 256>>>(pt, ln2g + l * D_, ln2b + l * D_);
    }

    pool_kernel<<<B_, 256>>>(lens, out_w, out_b, out);
}